// round 10
// baseline (speedup 1.0000x reference)
#include <cuda_runtime.h>
#include <cuda_fp16.h>
#include <math.h>
#include <stdint.h>

#define T_   16
#define SPA  2048
#define C_   768
#define NH   12
#define HD   64
#define N1   2304
#define M_   (T_*SPA)   // 32768

// ---------------- scratch (static device allocations) ----------------------
__device__ float g_rstd[T_*NH];
__device__ float g_qkv[(size_t)SPA*NH*T_*192];
__device__ __half g_ah[(size_t)M_*C_];
__device__ __half g_wih[(size_t)N1*C_];
__device__ __half g_woh[(size_t)C_*C_];
__device__ __half g_oh[(size_t)M_*C_];

// ---------------- helpers ---------------------------------------------------
static __device__ __forceinline__ uint32_t smem_u32(const void* p) {
    uint32_t a;
    asm("{ .reg .u64 t; cvta.to.shared.u64 t, %1; cvt.u32.u64 %0, t; }" : "=r"(a) : "l"(p));
    return a;
}

#define CP16(smem, gp) \
    asm volatile("cp.async.cg.shared.global [%0], [%1], 16;" :: "r"(smem), "l"(gp) : "memory")
#define CP_COMMIT() asm volatile("cp.async.commit_group;" ::: "memory")
#define CP_WAIT1()  asm volatile("cp.async.wait_group 1;" ::: "memory")
#define CP_WAIT0()  asm volatile("cp.async.wait_group 0;" ::: "memory")

#define LDSM4(r, addr) \
    asm volatile("ldmatrix.sync.aligned.m8n8.x4.shared.b16 {%0,%1,%2,%3}, [%4];" \
        : "=r"((r)[0]), "=r"((r)[1]), "=r"((r)[2]), "=r"((r)[3]) : "r"(addr))

#define MMAH(d, a, b0, b1) \
    asm volatile("mma.sync.aligned.m16n8k16.row.col.f32.f16.f16.f32 " \
        "{%0,%1,%2,%3}, {%4,%5,%6,%7}, {%8,%9}, {%0,%1,%2,%3};" \
        : "+f"((d)[0]), "+f"((d)[1]), "+f"((d)[2]), "+f"((d)[3]) \
        : "r"((a)[0]), "r"((a)[1]), "r"((a)[2]), "r"((a)[3]), "r"(b0), "r"(b1))

#define STAGE_BYTES 49152   // A 256x128B = 32KB | B 128x128B = 16KB (k64 chunk)
#define NSTAGE 3
#define SMEM_GEMM (NSTAGE*STAGE_BYTES)   // 147456

// ---------------------------------------------------------------------------
// Kernel 1: RMS groupnorm stats
// ---------------------------------------------------------------------------
__global__ void gn_stats_kernel(const float* __restrict__ x) {
    int g = blockIdx.x % NH, t = blockIdx.x / NH;
    const float4* p = (const float4*)(x + (size_t)t*C_*SPA + (size_t)g*HD*SPA);
    float ss = 0.f;
    for (int i = threadIdx.x; i < (HD*SPA)/4; i += blockDim.x) {
        float4 v = p[i];
        ss += v.x*v.x + v.y*v.y + v.z*v.z + v.w*v.w;
    }
    __shared__ float red[256];
    red[threadIdx.x] = ss;
    __syncthreads();
    for (int o = 128; o > 0; o >>= 1) {
        if (threadIdx.x < o) red[threadIdx.x] += red[threadIdx.x + o];
        __syncthreads();
    }
    if (threadIdx.x == 0)
        g_rstd[t*NH + g] = rsqrtf(red[0] * (1.f/(HD*SPA)) + 1e-6f);
}

// ---------------------------------------------------------------------------
// Kernel 2: transpose + scale + fp16 x -> g_ah  [m=(t,s)][c]
// ---------------------------------------------------------------------------
__global__ void prep_x_kernel(const float* __restrict__ x, const float* __restrict__ nw) {
    __shared__ float tile[64][65];
    int bm = blockIdx.x * 64, c0 = blockIdx.y * 64;
    int t = bm >> 11, s0 = bm & (SPA-1);
    int tid = threadIdx.x;
    int sl = tid & 63, cb = tid >> 6;
    #pragma unroll
    for (int r = 0; r < 16; r++) {
        int c = cb*16 + r, cg = c0 + c;
        float sc = g_rstd[t*NH + (cg >> 6)] * nw[cg];
        tile[sl][c] = x[(size_t)t*C_*SPA + (size_t)cg*SPA + s0 + sl] * sc;
    }
    __syncthreads();
    int cl = tid & 31, mb = tid >> 5;
    #pragma unroll
    for (int r = 0; r < 8; r++) {
        int m = mb*8 + r;
        __half2 h = __floats2half2_rn(tile[m][2*cl], tile[m][2*cl+1]);
        ((__half2*)g_ah)[(size_t)(bm+m)*(C_/2) + (c0 >> 1) + cl] = h;
    }
}

// ---------------------------------------------------------------------------
// Kernel 3: fp16 conversion of both weight matrices
// ---------------------------------------------------------------------------
__global__ void prep_w_kernel(const float* __restrict__ win, const float* __restrict__ wout) {
    int i = blockIdx.x * 256 + threadIdx.x;
    const int NI = N1*C_/4;
    float4 v; unsigned* dh; int j;
    if (i < NI) { v = ((const float4*)win)[i]; dh = (unsigned*)g_wih; j = i; }
    else        { j = i - NI; v = ((const float4*)wout)[j]; dh = (unsigned*)g_woh; }
    __half2 h0 = __floats2half2_rn(v.x, v.y);
    __half2 h1 = __floats2half2_rn(v.z, v.w);
    dh[2*j]   = *(unsigned*)&h0;
    dh[2*j+1] = *(unsigned*)&h1;
}

// ---------------------------------------------------------------------------
// MMA mainloop: CTA 256x128, 8 warps (4m x 2n), warp tile 64x64.
// K=768 as 12 k64 chunks; 3-stage cp.async, prefetch distance 2.
// Stage: A(256 rows x 128B) at +0, B(128 rows x 128B) at +32768. SW128.
// ---------------------------------------------------------------------------
static __device__ __forceinline__ void stage_fill(uint32_t dst, const char* aRow,
                                                  const char* bRow, int tid) {
    uint32_t xa = (uint32_t)((tid & 7) << 4);
    uint32_t da = dst + (uint32_t)(tid * 128);
    #pragma unroll
    for (int i = 0; i < 8; i++)
        CP16(da + (((uint32_t)(i << 4)) ^ xa), aRow + i*16);
    int br = tid >> 1, part = tid & 1;
    uint32_t xb = (uint32_t)((br & 7) << 4);
    uint32_t db = dst + 32768 + (uint32_t)(br * 128);
    #pragma unroll
    for (int i = 0; i < 4; i++)
        CP16(db + (((uint32_t)((part << 6) | (i << 4))) ^ xb), bRow + i*16);
    CP_COMMIT();
}

static __device__ __forceinline__ void mma_mainloop(
        float acc[4][8][4], const char* aSrc, const char* bSrc, uint32_t sb) {
    int tid = threadIdx.x;
    int lid = tid & 31, wid = tid >> 5;
    int wm = (wid & 3) * 64, wn = (wid >> 2) * 64;

    uint32_t xr   = (uint32_t)((lid & 7) << 4);
    uint32_t aSel = (uint32_t)(((lid >> 4) & 1) << 4);
    uint32_t bSel = (uint32_t)(((lid >> 3) & 1) << 4);
    uint32_t arb[4], brb[4];
    #pragma unroll
    for (int mt = 0; mt < 4; mt++)
        arb[mt] = (uint32_t)((wm + mt*16 + (lid & 15)) * 128);
    #pragma unroll
    for (int nt = 0; nt < 4; nt++)
        brb[nt] = 32768u + (uint32_t)((wn + nt*16 + (lid & 7) + (((lid >> 4) & 1) << 3)) * 128);

    // prologue: stage 0 <- chunk 0, stage 1 <- chunk 1
    stage_fill(sb,               aSrc,       bSrc,       tid);
    stage_fill(sb + STAGE_BYTES, aSrc + 128, bSrc + 128, tid);

    for (int c = 0; c < 12; c++) {
        if (c == 11) CP_WAIT0(); else CP_WAIT1();   // chunk c landed
        __syncthreads();
        if (c + 2 < 12) {
            int st = (c + 2) % NSTAGE;
            stage_fill(sb + (uint32_t)(st * STAGE_BYTES),
                       aSrc + (size_t)(c+2)*128, bSrc + (size_t)(c+2)*128, tid);
        }
        uint32_t bo = (uint32_t)((c % NSTAGE) * STAGE_BYTES);
        #pragma unroll
        for (int kk = 0; kk < 4; kk++) {
            uint32_t cb = (uint32_t)(kk << 5);
            uint32_t ah[4][4];
            #pragma unroll
            for (int mt = 0; mt < 4; mt++)
                LDSM4(ah[mt], sb + bo + arb[mt] + ((cb | aSel) ^ xr));
            #pragma unroll
            for (int nt = 0; nt < 4; nt++) {
                uint32_t bh[4];
                LDSM4(bh, sb + bo + brb[nt] + ((cb | bSel) ^ xr));
                #pragma unroll
                for (int n8 = 0; n8 < 2; n8++)
                    #pragma unroll
                    for (int mt = 0; mt < 4; mt++)
                        MMAH(acc[mt][nt*2+n8], ah[mt], bh[n8*2], bh[n8*2+1]);
            }
        }
    }
}

// Stage one 128-row half of the 256x128 acc tile into smem [128][132] f32.
static __device__ __forceinline__ void stage_acc_half(float acc[4][8][4], float* st, int half) {
    int tid = threadIdx.x, lid = tid & 31, wid = tid >> 5;
    int wrow = wid & 3, wn = (wid >> 2) * 64;
    int qr = lid >> 2, qc = (lid & 3) * 2;
    if ((wrow >> 1) == half) {
        int lm = (wrow & 1) * 64;
        #pragma unroll
        for (int mt = 0; mt < 4; mt++)
            #pragma unroll
            for (int n8 = 0; n8 < 8; n8++) {
                float* p0 = st + (lm + mt*16 + qr)*132 + wn + n8*8 + qc;
                p0[0] = acc[mt][n8][0];
                p0[1] = acc[mt][n8][1];
                p0[8*132]   = acc[mt][n8][2];
                p0[8*132+1] = acc[mt][n8][3];
            }
    }
}

// ---------------------------------------------------------------------------
// Kernel 4: QKV GEMM. grid = (N1/128 = 18, M_/256 = 128)
// ---------------------------------------------------------------------------
__global__ void __launch_bounds__(256, 1) qkv_gemm_tc(const float* __restrict__ bias) {
    extern __shared__ char smem[];
    uint32_t sb = smem_u32(smem);
    int tid = threadIdx.x;
    int bn = blockIdx.x * 128, bm = blockIdx.y * 256;
    const char* aSrc = (const char*)(g_ah  + (size_t)(bm + tid)*C_);
    const char* bSrc = (const char*)(g_wih + (size_t)(bn + (tid >> 1))*C_) + (tid & 1)*64;

    float acc[4][8][4] = {};
    mma_mainloop(acc, aSrc, bSrc, sb);

    float* st = (float*)smem;
    int t = bm >> 11, s0 = bm & (SPA-1);
    int n0 = bn + (tid & 1) * 64;
    int h = n0 / 192, j0 = n0 % 192;
    #pragma unroll
    for (int half = 0; half < 2; half++) {
        __syncthreads();
        stage_acc_half(acc, st, half);
        __syncthreads();
        int s = s0 + half*128 + (tid >> 1);
        float* dst = &g_qkv[(((size_t)s*NH + h)*T_ + t)*192 + j0];
        const float* src = st + (tid >> 1)*132 + (tid & 1)*64;
        #pragma unroll
        for (int i = 0; i < 16; i++) {
            float4 v  = *(const float4*)(src + i*4);
            float4 bv = *(const float4*)(bias + n0 + i*4);
            v.x += bv.x; v.y += bv.y; v.z += bv.z; v.w += bv.w;
            *(float4*)(dst + i*4) = v;
        }
    }
}

// ---------------------------------------------------------------------------
// Kernel 5: attention (fp32), writes fp16 output for out GEMM
// ---------------------------------------------------------------------------
__global__ void attn_kernel(const float* __restrict__ qsc, const float* __restrict__ qbi,
                            const float* __restrict__ ksc, const float* __restrict__ kbi,
                            const float* __restrict__ tab) {
    int sh = blockIdx.x;
    int h = sh % NH, s = sh / NH;
    __shared__ float qs[16][65], ks[16][65], vs[16][65], P[16][17];
    int tid = threadIdx.x;
    int row = tid >> 3, part = tid & 7;
    const float* base = g_qkv + (size_t)sh*(T_*192) + row*192 + part*8;

    {
        float v0[8];
        #pragma unroll
        for (int e = 0; e < 8; e++) v0[e] = base[e];
        float sum = 0.f;
        #pragma unroll
        for (int e = 0; e < 8; e++) sum += v0[e];
        sum += __shfl_xor_sync(~0u, sum, 1); sum += __shfl_xor_sync(~0u, sum, 2); sum += __shfl_xor_sync(~0u, sum, 4);
        float mu = sum * (1.f/64.f), var = 0.f;
        #pragma unroll
        for (int e = 0; e < 8; e++) { float d = v0[e]-mu; var += d*d; }
        var += __shfl_xor_sync(~0u, var, 1); var += __shfl_xor_sync(~0u, var, 2); var += __shfl_xor_sync(~0u, var, 4);
        float rr = rsqrtf(var * (1.f/64.f) + 1e-6f);
        #pragma unroll
        for (int e = 0; e < 8; e++) { int j = part*8+e; qs[row][j] = (v0[e]-mu)*rr*qsc[j] + qbi[j]; }
    }
    {
        float v0[8];
        #pragma unroll
        for (int e = 0; e < 8; e++) v0[e] = base[64+e];
        float sum = 0.f;
        #pragma unroll
        for (int e = 0; e < 8; e++) sum += v0[e];
        sum += __shfl_xor_sync(~0u, sum, 1); sum += __shfl_xor_sync(~0u, sum, 2); sum += __shfl_xor_sync(~0u, sum, 4);
        float mu = sum * (1.f/64.f), var = 0.f;
        #pragma unroll
        for (int e = 0; e < 8; e++) { float d = v0[e]-mu; var += d*d; }
        var += __shfl_xor_sync(~0u, var, 1); var += __shfl_xor_sync(~0u, var, 2); var += __shfl_xor_sync(~0u, var, 4);
        float rr = rsqrtf(var * (1.f/64.f) + 1e-6f);
        #pragma unroll
        for (int e = 0; e < 8; e++) { int j = part*8+e; ks[row][j] = (v0[e]-mu)*rr*ksc[j] + kbi[j]; }
    }
    #pragma unroll
    for (int e = 0; e < 8; e++) vs[row][part*8+e] = base[128+e];
    __syncthreads();

    const float inv_log16_x8 = 8.f / logf(16.f);
    for (int e = tid; e < 256; e += 128) {
        int i = e >> 4, j = e & 15;
        float d = 0.f;
        #pragma unroll
        for (int c = 0; c < 64; c++) d += qs[i][c]*ks[j][c];
        int rp = j - i;
        int ret = (rp > 0) ? 16 : 0;
        int n = rp < 0 ? -rp : rp;
        int bkt;
        if (n < 8) bkt = ret + n;
        else {
            int vl = 8 + (int)(logf((float)n * 0.125f) * inv_log16_x8);
            bkt = ret + (vl < 15 ? vl : 15);
        }
        P[i][j] = d * 0.125f + tab[bkt*NH + h];
    }
    __syncthreads();
    if (tid < 16) {
        float m = -1e30f;
        #pragma unroll
        for (int j = 0; j < 16; j++) m = fmaxf(m, P[tid][j]);
        float sum = 0.f;
        #pragma unroll
        for (int j = 0; j < 16; j++) { float e = expf(P[tid][j]-m); P[tid][j] = e; sum += e; }
        float inv = 1.f / sum;
        #pragma unroll
        for (int j = 0; j < 16; j++) P[tid][j] *= inv;
    }
    __syncthreads();

    float o[8] = {0,0,0,0,0,0,0,0};
    #pragma unroll
    for (int t2 = 0; t2 < 16; t2++) {
        float p = P[row][t2];
        #pragma unroll
        for (int e = 0; e < 8; e++) o[e] += p * vs[t2][part*8+e];
    }
    unsigned H[4];
    #pragma unroll
    for (int e = 0; e < 4; e++) {
        __half2 hh = __floats2half2_rn(o[2*e], o[2*e+1]);
        H[e] = *(unsigned*)&hh;
    }
    size_t off = ((size_t)row*SPA + s)*C_ + h*HD + part*8;
    *(uint4*)(g_oh + off) = make_uint4(H[0], H[1], H[2], H[3]);
}

// ---------------------------------------------------------------------------
// Kernel 6: output GEMM + bias + residual. grid = (C_/128 = 6, M_/256 = 128)
// ---------------------------------------------------------------------------
__global__ void __launch_bounds__(256, 1) out_gemm_tc(const float* __restrict__ x,
                                                      const float* __restrict__ bias,
                                                      float* __restrict__ y) {
    extern __shared__ char smem[];
    uint32_t sb = smem_u32(smem);
    int tid = threadIdx.x;
    int bn = blockIdx.x * 128, bm = blockIdx.y * 256;
    const char* aSrc = (const char*)(g_oh  + (size_t)(bm + tid)*C_);
    const char* bSrc = (const char*)(g_woh + (size_t)(bn + (tid >> 1))*C_) + (tid & 1)*64;

    float acc[4][8][4] = {};
    mma_mainloop(acc, aSrc, bSrc, sb);

    float* st = (float*)smem;
    int t = bm >> 11, s0 = bm & (SPA-1);
    int n = bn + (tid >> 1);
    int sh_ = tid & 1;
    float bb = bias[n];
    #pragma unroll
    for (int half = 0; half < 2; half++) {
        __syncthreads();
        stage_acc_half(acc, st, half);
        __syncthreads();
        size_t off = (size_t)t*C_*SPA + (size_t)n*SPA + s0 + half*128 + sh_*64;
        const float* src = st + sh_*64*132 + (n - bn);
        #pragma unroll
        for (int i = 0; i < 64; i += 4) {
            float4 rx = *(const float4*)(x + off + i);
            float4 v = make_float4(src[(i+0)*132], src[(i+1)*132],
                                   src[(i+2)*132], src[(i+3)*132]);
            v.x += bb + rx.x; v.y += bb + rx.y; v.z += bb + rx.z; v.w += bb + rx.w;
            *(float4*)(y + off + i) = v;
        }
    }
}

// ---------------------------------------------------------------------------
extern "C" void kernel_launch(void* const* d_in, const int* in_sizes, int n_in,
                              void* d_out, int out_size) {
    const float* x     = (const float*)d_in[0];
    const float* nw    = (const float*)d_in[1];
    const float* w_in  = (const float*)d_in[2];
    const float* b_in  = (const float*)d_in[3];
    const float* qsc   = (const float*)d_in[4];
    const float* qbi   = (const float*)d_in[5];
    const float* ksc   = (const float*)d_in[6];
    const float* kbi   = (const float*)d_in[7];
    const float* tab   = (const float*)d_in[8];
    const float* w_out = (const float*)d_in[9];
    const float* b_out = (const float*)d_in[10];
    float* y = (float*)d_out;

    cudaFuncSetAttribute(qkv_gemm_tc, cudaFuncAttributeMaxDynamicSharedMemorySize, SMEM_GEMM);
    cudaFuncSetAttribute(out_gemm_tc, cudaFuncAttributeMaxDynamicSharedMemorySize, SMEM_GEMM);

    gn_stats_kernel<<<T_*NH, 256>>>(x);
    prep_w_kernel<<<(N1*C_/4 + C_*C_/4)/256, 256>>>(w_in, w_out);
    prep_x_kernel<<<dim3(M_/64, C_/64), 256>>>(x, nw);
    qkv_gemm_tc<<<dim3(N1/128, M_/256), 256, SMEM_GEMM>>>(b_in);
    attn_kernel<<<SPA*NH, 128>>>(qsc, qbi, ksc, kbi, tab);
    out_gemm_tc<<<dim3(C_/128, M_/256), 256, SMEM_GEMM>>>(x, b_out, y);
}

// round 11
// speedup vs baseline: 1.1087x; 1.1087x over previous
#include <cuda_runtime.h>
#include <cuda_fp16.h>
#include <math.h>
#include <stdint.h>

#define T_   16
#define SPA  2048
#define C_   768
#define NH   12
#define HD   64
#define N1   2304
#define M_   (T_*SPA)   // 32768

// ---------------- scratch (static device allocations) ----------------------
__device__ float g_rstd[T_*NH];
__device__ float g_qkv[(size_t)SPA*NH*T_*192];
__device__ __half g_ah[(size_t)M_*C_];
__device__ __half g_wih[(size_t)N1*C_];
__device__ __half g_woh[(size_t)C_*C_];
__device__ __half g_oh[(size_t)M_*C_];

// ---------------- helpers ---------------------------------------------------
static __device__ __forceinline__ uint32_t smem_u32(const void* p) {
    uint32_t a;
    asm("{ .reg .u64 t; cvta.to.shared.u64 t, %1; cvt.u32.u64 %0, t; }" : "=r"(a) : "l"(p));
    return a;
}

#define CP16(smem, gp) \
    asm volatile("cp.async.cg.shared.global [%0], [%1], 16;" :: "r"(smem), "l"(gp) : "memory")
#define CP_COMMIT() asm volatile("cp.async.commit_group;" ::: "memory")
#define CP_WAIT1()  asm volatile("cp.async.wait_group 1;" ::: "memory")
#define CP_WAIT0()  asm volatile("cp.async.wait_group 0;" ::: "memory")

#define LDSM4(r, addr) \
    asm volatile("ldmatrix.sync.aligned.m8n8.x4.shared.b16 {%0,%1,%2,%3}, [%4];" \
        : "=r"((r)[0]), "=r"((r)[1]), "=r"((r)[2]), "=r"((r)[3]) : "r"(addr))

#define MMAH(d, a, b0, b1) \
    asm volatile("mma.sync.aligned.m16n8k16.row.col.f32.f16.f16.f32 " \
        "{%0,%1,%2,%3}, {%4,%5,%6,%7}, {%8,%9}, {%0,%1,%2,%3};" \
        : "+f"((d)[0]), "+f"((d)[1]), "+f"((d)[2]), "+f"((d)[3]) \
        : "r"((a)[0]), "r"((a)[1]), "r"((a)[2]), "r"((a)[3]), "r"(b0), "r"(b1))

#define STAGE_BYTES 32768            // A 16KB | B 16KB  (k64 chunk)
#define NSTAGE 3
#define SMEM_GEMM (NSTAGE*STAGE_BYTES)   // 98304 (>= epilogue 67584)

// ---------------------------------------------------------------------------
// Kernel 1: RMS groupnorm stats
// ---------------------------------------------------------------------------
__global__ void gn_stats_kernel(const float* __restrict__ x) {
    int g = blockIdx.x % NH, t = blockIdx.x / NH;
    const float4* p = (const float4*)(x + (size_t)t*C_*SPA + (size_t)g*HD*SPA);
    float ss = 0.f;
    for (int i = threadIdx.x; i < (HD*SPA)/4; i += blockDim.x) {
        float4 v = p[i];
        ss += v.x*v.x + v.y*v.y + v.z*v.z + v.w*v.w;
    }
    __shared__ float red[256];
    red[threadIdx.x] = ss;
    __syncthreads();
    for (int o = 128; o > 0; o >>= 1) {
        if (threadIdx.x < o) red[threadIdx.x] += red[threadIdx.x + o];
        __syncthreads();
    }
    if (threadIdx.x == 0)
        g_rstd[t*NH + g] = rsqrtf(red[0] * (1.f/(HD*SPA)) + 1e-6f);
}

// ---------------------------------------------------------------------------
// Kernel 2: transpose + scale + fp16 x -> g_ah  [m=(t,s)][c]
// ---------------------------------------------------------------------------
__global__ void prep_x_kernel(const float* __restrict__ x, const float* __restrict__ nw) {
    __shared__ float tile[64][65];
    int bm = blockIdx.x * 64, c0 = blockIdx.y * 64;
    int t = bm >> 11, s0 = bm & (SPA-1);
    int tid = threadIdx.x;
    int sl = tid & 63, cb = tid >> 6;
    #pragma unroll
    for (int r = 0; r < 16; r++) {
        int c = cb*16 + r, cg = c0 + c;
        float sc = g_rstd[t*NH + (cg >> 6)] * nw[cg];
        tile[sl][c] = x[(size_t)t*C_*SPA + (size_t)cg*SPA + s0 + sl] * sc;
    }
    __syncthreads();
    int cl = tid & 31, mb = tid >> 5;
    #pragma unroll
    for (int r = 0; r < 8; r++) {
        int m = mb*8 + r;
        __half2 h = __floats2half2_rn(tile[m][2*cl], tile[m][2*cl+1]);
        ((__half2*)g_ah)[(size_t)(bm+m)*(C_/2) + (c0 >> 1) + cl] = h;
    }
}

// ---------------------------------------------------------------------------
// Kernel 3: fp16 conversion of both weight matrices
// ---------------------------------------------------------------------------
__global__ void prep_w_kernel(const float* __restrict__ win, const float* __restrict__ wout) {
    int i = blockIdx.x * 256 + threadIdx.x;
    const int NI = N1*C_/4;
    float4 v; unsigned* dh; int j;
    if (i < NI) { v = ((const float4*)win)[i]; dh = (unsigned*)g_wih; j = i; }
    else        { j = i - NI; v = ((const float4*)wout)[j]; dh = (unsigned*)g_woh; }
    __half2 h0 = __floats2half2_rn(v.x, v.y);
    __half2 h1 = __floats2half2_rn(v.z, v.w);
    dh[2*j]   = *(unsigned*)&h0;
    dh[2*j+1] = *(unsigned*)&h1;
}

// ---------------------------------------------------------------------------
// MMA mainloop: CTA 128x128, K=768 as 12 k64 chunks, 3-stage cp.async,
// prefetch distance 2, wait_group 1 (loads get 2 chunks of slack).
// Stage: A(128x128B) | B(128x128B), SW128. fp16 x fp16, fp32 accum.
// ---------------------------------------------------------------------------
static __device__ __forceinline__ void stage_fill(uint32_t dst, const char* ap,
                                                  const char* bp, uint32_t xld, int part) {
    #pragma unroll
    for (int i = 0; i < 4; i++) {
        uint32_t o = (uint32_t)((part << 6) | (i << 4)) ^ xld;
        CP16(dst + o,         ap + i*16);
        CP16(dst + 16384 + o, bp + i*16);
    }
    CP_COMMIT();
}

static __device__ __forceinline__ void mma_mainloop(
        float acc[2][8][4], const char* aSrc, const char* bSrc, uint32_t sb) {
    int tid = threadIdx.x;
    int lid = tid & 31, wid = tid >> 5;
    int wm = (wid & 3) * 32, wn = (wid >> 2) * 64;
    int r  = tid >> 1, part = tid & 1;

    uint32_t stRow = (uint32_t)(r * 128);
    uint32_t xld   = (uint32_t)((r & 7) << 4);
    uint32_t xr    = (uint32_t)((lid & 7) << 4);
    uint32_t aSel  = (uint32_t)(((lid >> 4) & 1) << 4);
    uint32_t bSel  = (uint32_t)(((lid >> 3) & 1) << 4);
    uint32_t arb[2], brb[4];
    #pragma unroll
    for (int mt = 0; mt < 2; mt++)
        arb[mt] = (uint32_t)((wm + mt*16 + (lid & 15)) * 128);
    #pragma unroll
    for (int nt = 0; nt < 4; nt++)
        brb[nt] = (uint32_t)((wn + nt*16 + (lid & 7) + (((lid >> 4) & 1) << 3)) * 128);

    // prologue: stage 0 <- chunk 0, stage 1 <- chunk 1
    stage_fill(sb + stRow,               aSrc,       bSrc,       xld, part);
    stage_fill(sb + STAGE_BYTES + stRow, aSrc + 128, bSrc + 128, xld, part);

    for (int c = 0; c < 12; c++) {
        if (c == 11) CP_WAIT0(); else CP_WAIT1();   // chunk c landed
        __syncthreads();     // all warps done reading stage (c+2)%3 (read at c-1)
        if (c + 2 < 12) {
            int st = (c + 2) % NSTAGE;
            stage_fill(sb + (uint32_t)(st * STAGE_BYTES) + stRow,
                       aSrc + (size_t)(c+2)*128, bSrc + (size_t)(c+2)*128, xld, part);
        }
        uint32_t bo = (uint32_t)((c % NSTAGE) * STAGE_BYTES);
        #pragma unroll
        for (int kk = 0; kk < 4; kk++) {
            uint32_t cb = (uint32_t)(kk << 5);
            uint32_t ah[2][4];
            #pragma unroll
            for (int mt = 0; mt < 2; mt++)
                LDSM4(ah[mt], sb + bo + arb[mt] + ((cb | aSel) ^ xr));
            #pragma unroll
            for (int nt = 0; nt < 4; nt++) {
                uint32_t bh[4];
                LDSM4(bh, sb + bo + 16384 + brb[nt] + ((cb | bSel) ^ xr));
                #pragma unroll
                for (int n8 = 0; n8 < 2; n8++)
                    #pragma unroll
                    for (int mt = 0; mt < 2; mt++)
                        MMAH(acc[mt][nt*2+n8], ah[mt], bh[n8*2], bh[n8*2+1]);
            }
        }
    }
}

// Stage accumulators into smem as [128][132] f32 (67584 bytes)
static __device__ __forceinline__ void stage_acc(float acc[2][8][4], float* st) {
    int tid = threadIdx.x, lid = tid & 31, wid = tid >> 5;
    int wm = (wid & 3) * 32, wn = (wid >> 2) * 64;
    int qr = lid >> 2, qc = (lid & 3) * 2;
    #pragma unroll
    for (int mt = 0; mt < 2; mt++)
        #pragma unroll
        for (int n8 = 0; n8 < 8; n8++) {
            float* p0 = st + (wm + mt*16 + qr)*132 + wn + n8*8 + qc;
            p0[0] = acc[mt][n8][0];
            p0[1] = acc[mt][n8][1];
            p0[8*132]   = acc[mt][n8][2];
            p0[8*132+1] = acc[mt][n8][3];
        }
}

// ---------------------------------------------------------------------------
// Kernel 4: QKV GEMM. grid = (18, 256)
// ---------------------------------------------------------------------------
__global__ void __launch_bounds__(256, 2) qkv_gemm_tc(const float* __restrict__ bias) {
    extern __shared__ char smem[];
    uint32_t sb = smem_u32(smem);
    int tid = threadIdx.x;
    int bn = blockIdx.x * 128, bm = blockIdx.y * 128;
    int r = tid >> 1, part = tid & 1;
    const char* aSrc = (const char*)(g_ah  + (size_t)(bm + r)*C_) + part*64;
    const char* bSrc = (const char*)(g_wih + (size_t)(bn + r)*C_) + part*64;

    float acc[2][8][4] = {};
    mma_mainloop(acc, aSrc, bSrc, sb);
    __syncthreads();
    float* st = (float*)smem;
    stage_acc(acc, st);
    __syncthreads();

    int t = bm >> 11, s = (bm & (SPA-1)) + (tid >> 1);
    int n0 = bn + (tid & 1) * 64;
    int h = n0 / 192, j0 = n0 % 192;
    float* dst = &g_qkv[(((size_t)s*NH + h)*T_ + t)*192 + j0];
    const float* src = st + (tid >> 1)*132 + (tid & 1)*64;
    #pragma unroll
    for (int i = 0; i < 16; i++) {
        float4 v  = *(const float4*)(src + i*4);
        float4 bv = *(const float4*)(bias + n0 + i*4);
        v.x += bv.x; v.y += bv.y; v.z += bv.z; v.w += bv.w;
        *(float4*)(dst + i*4) = v;
    }
}

// ---------------------------------------------------------------------------
// Kernel 5: attention (fp32), writes fp16 output for out GEMM
// ---------------------------------------------------------------------------
__global__ void attn_kernel(const float* __restrict__ qsc, const float* __restrict__ qbi,
                            const float* __restrict__ ksc, const float* __restrict__ kbi,
                            const float* __restrict__ tab) {
    int sh = blockIdx.x;
    int h = sh % NH, s = sh / NH;
    __shared__ float qs[16][65], ks[16][65], vs[16][65], P[16][17];
    int tid = threadIdx.x;
    int row = tid >> 3, part = tid & 7;
    const float* base = g_qkv + (size_t)sh*(T_*192) + row*192 + part*8;

    {
        float v0[8];
        #pragma unroll
        for (int e = 0; e < 8; e++) v0[e] = base[e];
        float sum = 0.f;
        #pragma unroll
        for (int e = 0; e < 8; e++) sum += v0[e];
        sum += __shfl_xor_sync(~0u, sum, 1); sum += __shfl_xor_sync(~0u, sum, 2); sum += __shfl_xor_sync(~0u, sum, 4);
        float mu = sum * (1.f/64.f), var = 0.f;
        #pragma unroll
        for (int e = 0; e < 8; e++) { float d = v0[e]-mu; var += d*d; }
        var += __shfl_xor_sync(~0u, var, 1); var += __shfl_xor_sync(~0u, var, 2); var += __shfl_xor_sync(~0u, var, 4);
        float rr = rsqrtf(var * (1.f/64.f) + 1e-6f);
        #pragma unroll
        for (int e = 0; e < 8; e++) { int j = part*8+e; qs[row][j] = (v0[e]-mu)*rr*qsc[j] + qbi[j]; }
    }
    {
        float v0[8];
        #pragma unroll
        for (int e = 0; e < 8; e++) v0[e] = base[64+e];
        float sum = 0.f;
        #pragma unroll
        for (int e = 0; e < 8; e++) sum += v0[e];
        sum += __shfl_xor_sync(~0u, sum, 1); sum += __shfl_xor_sync(~0u, sum, 2); sum += __shfl_xor_sync(~0u, sum, 4);
        float mu = sum * (1.f/64.f), var = 0.f;
        #pragma unroll
        for (int e = 0; e < 8; e++) { float d = v0[e]-mu; var += d*d; }
        var += __shfl_xor_sync(~0u, var, 1); var += __shfl_xor_sync(~0u, var, 2); var += __shfl_xor_sync(~0u, var, 4);
        float rr = rsqrtf(var * (1.f/64.f) + 1e-6f);
        #pragma unroll
        for (int e = 0; e < 8; e++) { int j = part*8+e; ks[row][j] = (v0[e]-mu)*rr*ksc[j] + kbi[j]; }
    }
    #pragma unroll
    for (int e = 0; e < 8; e++) vs[row][part*8+e] = base[128+e];
    __syncthreads();

    const float inv_log16_x8 = 8.f / logf(16.f);
    for (int e = tid; e < 256; e += 128) {
        int i = e >> 4, j = e & 15;
        float d = 0.f;
        #pragma unroll
        for (int c = 0; c < 64; c++) d += qs[i][c]*ks[j][c];
        int rp = j - i;
        int ret = (rp > 0) ? 16 : 0;
        int n = rp < 0 ? -rp : rp;
        int bkt;
        if (n < 8) bkt = ret + n;
        else {
            int vl = 8 + (int)(logf((float)n * 0.125f) * inv_log16_x8);
            bkt = ret + (vl < 15 ? vl : 15);
        }
        P[i][j] = d * 0.125f + tab[bkt*NH + h];
    }
    __syncthreads();
    if (tid < 16) {
        float m = -1e30f;
        #pragma unroll
        for (int j = 0; j < 16; j++) m = fmaxf(m, P[tid][j]);
        float sum = 0.f;
        #pragma unroll
        for (int j = 0; j < 16; j++) { float e = expf(P[tid][j]-m); P[tid][j] = e; sum += e; }
        float inv = 1.f / sum;
        #pragma unroll
        for (int j = 0; j < 16; j++) P[tid][j] *= inv;
    }
    __syncthreads();

    float o[8] = {0,0,0,0,0,0,0,0};
    #pragma unroll
    for (int t2 = 0; t2 < 16; t2++) {
        float p = P[row][t2];
        #pragma unroll
        for (int e = 0; e < 8; e++) o[e] += p * vs[t2][part*8+e];
    }
    unsigned H[4];
    #pragma unroll
    for (int e = 0; e < 4; e++) {
        __half2 hh = __floats2half2_rn(o[2*e], o[2*e+1]);
        H[e] = *(unsigned*)&hh;
    }
    size_t off = ((size_t)row*SPA + s)*C_ + h*HD + part*8;
    *(uint4*)(g_oh + off) = make_uint4(H[0], H[1], H[2], H[3]);
}

// ---------------------------------------------------------------------------
// Kernel 6: output GEMM + bias + residual. grid = (6, 256)
// ---------------------------------------------------------------------------
__global__ void __launch_bounds__(256, 2) out_gemm_tc(const float* __restrict__ x,
                                                      const float* __restrict__ bias,
                                                      float* __restrict__ y) {
    extern __shared__ char smem[];
    uint32_t sb = smem_u32(smem);
    int tid = threadIdx.x;
    int bn = blockIdx.x * 128, bm = blockIdx.y * 128;
    int r = tid >> 1, part = tid & 1;
    const char* aSrc = (const char*)(g_oh  + (size_t)(bm + r)*C_) + part*64;
    const char* bSrc = (const char*)(g_woh + (size_t)(bn + r)*C_) + part*64;

    float acc[2][8][4] = {};
    mma_mainloop(acc, aSrc, bSrc, sb);
    __syncthreads();
    float* st = (float*)smem;
    stage_acc(acc, st);
    __syncthreads();

    int n = bn + (tid >> 1);
    int sh_ = tid & 1;
    int t = bm >> 11, s0 = bm & (SPA-1);
    size_t off = (size_t)t*C_*SPA + (size_t)n*SPA + s0 + sh_*64;
    float bb = bias[n];
    const float* src = st + sh_*64*132 + (n - bn);
    #pragma unroll
    for (int i = 0; i < 64; i += 4) {
        float4 rx = *(const float4*)(x + off + i);
        float4 v = make_float4(src[(i+0)*132], src[(i+1)*132],
                               src[(i+2)*132], src[(i+3)*132]);
        v.x += bb + rx.x; v.y += bb + rx.y; v.z += bb + rx.z; v.w += bb + rx.w;
        *(float4*)(y + off + i) = v;
    }
}

// ---------------------------------------------------------------------------
extern "C" void kernel_launch(void* const* d_in, const int* in_sizes, int n_in,
                              void* d_out, int out_size) {
    const float* x     = (const float*)d_in[0];
    const float* nw    = (const float*)d_in[1];
    const float* w_in  = (const float*)d_in[2];
    const float* b_in  = (const float*)d_in[3];
    const float* qsc   = (const float*)d_in[4];
    const float* qbi   = (const float*)d_in[5];
    const float* ksc   = (const float*)d_in[6];
    const float* kbi   = (const float*)d_in[7];
    const float* tab   = (const float*)d_in[8];
    const float* w_out = (const float*)d_in[9];
    const float* b_out = (const float*)d_in[10];
    float* y = (float*)d_out;

    cudaFuncSetAttribute(qkv_gemm_tc, cudaFuncAttributeMaxDynamicSharedMemorySize, SMEM_GEMM);
    cudaFuncSetAttribute(out_gemm_tc, cudaFuncAttributeMaxDynamicSharedMemorySize, SMEM_GEMM);

    gn_stats_kernel<<<T_*NH, 256>>>(x);
    prep_w_kernel<<<(N1*C_/4 + C_*C_/4)/256, 256>>>(w_in, w_out);
    prep_x_kernel<<<dim3(M_/64, C_/64), 256>>>(x, nw);
    qkv_gemm_tc<<<dim3(N1/128, M_/128), 256, SMEM_GEMM>>>(b_in);
    attn_kernel<<<SPA*NH, 128>>>(qsc, qbi, ksc, kbi, tab);
    out_gemm_tc<<<dim3(C_/128, M_/128), 256, SMEM_GEMM>>>(x, b_out, y);
}

// round 15
// speedup vs baseline: 1.2805x; 1.1550x over previous
#include <cuda_runtime.h>
#include <cuda_fp16.h>
#include <math.h>
#include <stdint.h>

#define T_   16
#define SPA  2048
#define C_   768
#define NH   12
#define HD   64
#define N1   2304
#define M_   (T_*SPA)   // 32768

// ---------------- scratch (static device allocations) ----------------------
__device__ float g_rstd[T_*NH];
__device__ __half g_qkv[(size_t)SPA*NH*T_*192];  // post-LN q,k + raw v (fp16)
__device__ __half g_ah[(size_t)M_*C_];
__device__ __half g_wih[(size_t)N1*C_];
__device__ __half g_woh[(size_t)C_*C_];
__device__ __half g_oh[(size_t)M_*C_];

// ---------------- helpers ---------------------------------------------------
static __device__ __forceinline__ uint32_t smem_u32(const void* p) {
    uint32_t a;
    asm("{ .reg .u64 t; cvta.to.shared.u64 t, %1; cvt.u32.u64 %0, t; }" : "=r"(a) : "l"(p));
    return a;
}

#define CP16(smem, gp) \
    asm volatile("cp.async.cg.shared.global [%0], [%1], 16;" :: "r"(smem), "l"(gp) : "memory")
#define CP_COMMIT() asm volatile("cp.async.commit_group;" ::: "memory")
#define CP_WAIT0()  asm volatile("cp.async.wait_group 0;" ::: "memory")

#define LDSM4(r, addr) \
    asm volatile("ldmatrix.sync.aligned.m8n8.x4.shared.b16 {%0,%1,%2,%3}, [%4];" \
        : "=r"((r)[0]), "=r"((r)[1]), "=r"((r)[2]), "=r"((r)[3]) : "r"(addr))

#define MMAH(d, a, b0, b1) \
    asm volatile("mma.sync.aligned.m16n8k16.row.col.f32.f16.f16.f32 " \
        "{%0,%1,%2,%3}, {%4,%5,%6,%7}, {%8,%9}, {%0,%1,%2,%3};" \
        : "+f"((d)[0]), "+f"((d)[1]), "+f"((d)[2]), "+f"((d)[3]) \
        : "r"((a)[0]), "r"((a)[1]), "r"((a)[2]), "r"((a)[3]), "r"(b0), "r"(b1))

#define STAGE_BYTES 32768            // A 16KB | B 16KB  (k64 chunk)
#define SMEM_GEMM   67584            // max(2 stages = 64KB, epilogue 128*132*4)

// ---------------------------------------------------------------------------
// Kernel 1: RMS groupnorm stats
// ---------------------------------------------------------------------------
__global__ void gn_stats_kernel(const float* __restrict__ x) {
    int g = blockIdx.x % NH, t = blockIdx.x / NH;
    const float4* p = (const float4*)(x + (size_t)t*C_*SPA + (size_t)g*HD*SPA);
    float ss = 0.f;
    for (int i = threadIdx.x; i < (HD*SPA)/4; i += blockDim.x) {
        float4 v = p[i];
        ss += v.x*v.x + v.y*v.y + v.z*v.z + v.w*v.w;
    }
    __shared__ float red[256];
    red[threadIdx.x] = ss;
    __syncthreads();
    for (int o = 128; o > 0; o >>= 1) {
        if (threadIdx.x < o) red[threadIdx.x] += red[threadIdx.x + o];
        __syncthreads();
    }
    if (threadIdx.x == 0)
        g_rstd[t*NH + g] = rsqrtf(red[0] * (1.f/(HD*SPA)) + 1e-6f);
}

// ---------------------------------------------------------------------------
// Kernel 2: transpose + scale + fp16 x -> g_ah  [m=(t,s)][c]
// ---------------------------------------------------------------------------
__global__ void prep_x_kernel(const float* __restrict__ x, const float* __restrict__ nw) {
    __shared__ float tile[64][65];
    int bm = blockIdx.x * 64, c0 = blockIdx.y * 64;
    int t = bm >> 11, s0 = bm & (SPA-1);
    int tid = threadIdx.x;
    int sl = tid & 63, cb = tid >> 6;
    #pragma unroll
    for (int r = 0; r < 16; r++) {
        int c = cb*16 + r, cg = c0 + c;
        float sc = g_rstd[t*NH + (cg >> 6)] * nw[cg];
        tile[sl][c] = x[(size_t)t*C_*SPA + (size_t)cg*SPA + s0 + sl] * sc;
    }
    __syncthreads();
    int cl = tid & 31, mb = tid >> 5;
    #pragma unroll
    for (int r = 0; r < 8; r++) {
        int m = mb*8 + r;
        __half2 h = __floats2half2_rn(tile[m][2*cl], tile[m][2*cl+1]);
        ((__half2*)g_ah)[(size_t)(bm+m)*(C_/2) + (c0 >> 1) + cl] = h;
    }
}

// ---------------------------------------------------------------------------
// Kernel 3: fp16 conversion of both weight matrices
// ---------------------------------------------------------------------------
__global__ void prep_w_kernel(const float* __restrict__ win, const float* __restrict__ wout) {
    int i = blockIdx.x * 256 + threadIdx.x;
    const int NI = N1*C_/4;
    float4 v; unsigned* dh; int j;
    if (i < NI) { v = ((const float4*)win)[i]; dh = (unsigned*)g_wih; j = i; }
    else        { j = i - NI; v = ((const float4*)wout)[j]; dh = (unsigned*)g_woh; }
    __half2 h0 = __floats2half2_rn(v.x, v.y);
    __half2 h1 = __floats2half2_rn(v.z, v.w);
    dh[2*j]   = *(unsigned*)&h0;
    dh[2*j+1] = *(unsigned*)&h1;
}

// ---------------------------------------------------------------------------
// MMA mainloop (r9 proven): CTA 128x128, 12 k64 chunks, 2-stage cp.async,
// single __syncthreads per chunk. fp16 x fp16, fp32 accum.
// ---------------------------------------------------------------------------
static __device__ __forceinline__ void stage_fill(uint32_t dst, const char* ap,
                                                  const char* bp, uint32_t xld, int part) {
    #pragma unroll
    for (int i = 0; i < 4; i++) {
        uint32_t o = (uint32_t)((part << 6) | (i << 4)) ^ xld;
        CP16(dst + o,         ap + i*16);
        CP16(dst + 16384 + o, bp + i*16);
    }
    CP_COMMIT();
}

static __device__ __forceinline__ void mma_mainloop(
        float acc[2][8][4], const char* aSrc, const char* bSrc, uint32_t sb) {
    int tid = threadIdx.x;
    int lid = tid & 31, wid = tid >> 5;
    int wm = (wid & 3) * 32, wn = (wid >> 2) * 64;
    int r  = tid >> 1, part = tid & 1;

    uint32_t stRow = (uint32_t)(r * 128);
    uint32_t xld   = (uint32_t)((r & 7) << 4);
    uint32_t xr    = (uint32_t)((lid & 7) << 4);
    uint32_t aSel  = (uint32_t)(((lid >> 4) & 1) << 4);
    uint32_t bSel  = (uint32_t)(((lid >> 3) & 1) << 4);
    uint32_t arb[2], brb[4];
    #pragma unroll
    for (int mt = 0; mt < 2; mt++)
        arb[mt] = (uint32_t)((wm + mt*16 + (lid & 15)) * 128);
    #pragma unroll
    for (int nt = 0; nt < 4; nt++)
        brb[nt] = (uint32_t)((wn + nt*16 + (lid & 7) + (((lid >> 4) & 1) << 3)) * 128);

    stage_fill(sb + stRow, aSrc, bSrc, xld, part);

    for (int c = 0; c < 12; c++) {
        CP_WAIT0();
        __syncthreads();
        if (c + 1 < 12) {
            stage_fill(sb + (uint32_t)(((c+1) & 1) * STAGE_BYTES) + stRow,
                       aSrc + (size_t)(c+1)*128, bSrc + (size_t)(c+1)*128, xld, part);
        }
        uint32_t bo = (uint32_t)((c & 1) * STAGE_BYTES);
        #pragma unroll
        for (int kk = 0; kk < 4; kk++) {
            uint32_t cb = (uint32_t)(kk << 5);
            uint32_t ah[2][4];
            #pragma unroll
            for (int mt = 0; mt < 2; mt++)
                LDSM4(ah[mt], sb + bo + arb[mt] + ((cb | aSel) ^ xr));
            #pragma unroll
            for (int nt = 0; nt < 4; nt++) {
                uint32_t bh[4];
                LDSM4(bh, sb + bo + 16384 + brb[nt] + ((cb | bSel) ^ xr));
                #pragma unroll
                for (int n8 = 0; n8 < 2; n8++)
                    #pragma unroll
                    for (int mt = 0; mt < 2; mt++)
                        MMAH(acc[mt][nt*2+n8], ah[mt], bh[n8*2], bh[n8*2+1]);
            }
        }
    }
}

// Stage accumulators into smem as [128][132] f32 (67584 bytes)
static __device__ __forceinline__ void stage_acc(float acc[2][8][4], float* st) {
    int tid = threadIdx.x, lid = tid & 31, wid = tid >> 5;
    int wm = (wid & 3) * 32, wn = (wid >> 2) * 64;
    int qr = lid >> 2, qc = (lid & 3) * 2;
    #pragma unroll
    for (int mt = 0; mt < 2; mt++)
        #pragma unroll
        for (int n8 = 0; n8 < 8; n8++) {
            float* p0 = st + (wm + mt*16 + qr)*132 + wn + n8*8 + qc;
            p0[0] = acc[mt][n8][0];
            p0[1] = acc[mt][n8][1];
            p0[8*132]   = acc[mt][n8][2];
            p0[8*132+1] = acc[mt][n8][3];
        }
}

// ---------------------------------------------------------------------------
// Kernel 4: QKV GEMM + fused bias + fused q/k layernorm + fp16 store.
// Each thread's 64 consecutive n-values = one full head vector (q, k or v).
// ---------------------------------------------------------------------------
__global__ void __launch_bounds__(256, 2) qkv_gemm_tc(
        const float* __restrict__ bias,
        const float* __restrict__ qsc, const float* __restrict__ qbi,
        const float* __restrict__ ksc, const float* __restrict__ kbi) {
    extern __shared__ char smem[];
    uint32_t sb = smem_u32(smem);
    int tid = threadIdx.x;
    int bn = blockIdx.x * 128, bm = blockIdx.y * 128;
    int r = tid >> 1, part = tid & 1;
    const char* aSrc = (const char*)(g_ah  + (size_t)(bm + r)*C_) + part*64;
    const char* bSrc = (const char*)(g_wih + (size_t)(bn + r)*C_) + part*64;

    float acc[2][8][4] = {};
    mma_mainloop(acc, aSrc, bSrc, sb);
    __syncthreads();
    float* st = (float*)smem;
    stage_acc(acc, st);
    __syncthreads();

    int t = bm >> 11, s = (bm & (SPA-1)) + (tid >> 1);
    int n0 = bn + (tid & 1) * 64;
    int h = n0 / 192, j0 = n0 % 192;
    const float* src = st + (tid >> 1)*132 + (tid & 1)*64;

    // pass 1: mean / var of (acc + bias) over the 64-dim head vector
    float sum = 0.f, sq = 0.f;
    #pragma unroll
    for (int j = 0; j < 64; j++) {
        float v = src[j] + __ldg(bias + n0 + j);
        sum += v; sq += v*v;
    }
    float mu = sum * (1.f/64.f);
    float var = sq * (1.f/64.f) - mu*mu;
    float rr = rsqrtf(var + 1e-6f);
    bool doLN = (j0 != 128);
    const float* sc = (j0 == 64) ? ksc : qsc;
    const float* bi = (j0 == 64) ? kbi : qbi;

    // pass 2: normalize (q/k) or passthrough (v), convert fp16, store 128B
    __half hb[64];
    #pragma unroll
    for (int j = 0; j < 64; j++) {
        float v = src[j] + __ldg(bias + n0 + j);
        float o = doLN ? ((v - mu)*rr*__ldg(sc + j) + __ldg(bi + j)) : v;
        hb[j] = __float2half_rn(o);
    }
    uint4* dst = (uint4*)&g_qkv[(((size_t)s*NH + h)*T_ + t)*192 + j0];
    #pragma unroll
    for (int i = 0; i < 8; i++) dst[i] = ((const uint4*)hb)[i];   // 64 halfs = 8 x uint4
}

// ---------------------------------------------------------------------------
// Kernel 5: attention — no LN (done in GEMM epilogue), fp16 in, fp16 out.
// ---------------------------------------------------------------------------
__global__ void attn_kernel(const float* __restrict__ tab) {
    int sh = blockIdx.x;
    int h = sh % NH, s = sh / NH;
    __shared__ float qs[16][65], ks[16][65], vs[16][65], P[16][17];
    int tid = threadIdx.x;
    int row = tid >> 3, part = tid & 7;
    const __half* base = g_qkv + (size_t)sh*(T_*192) + row*192 + part*8;

    uint4 qv = *(const uint4*)(base);
    uint4 kv = *(const uint4*)(base + 64);
    uint4 vv = *(const uint4*)(base + 128);
    const __half2* qh = (const __half2*)&qv;
    const __half2* kh = (const __half2*)&kv;
    const __half2* vh = (const __half2*)&vv;
    #pragma unroll
    for (int e = 0; e < 4; e++) {
        float2 fq = __half22float2(qh[e]);
        float2 fk = __half22float2(kh[e]);
        float2 fv = __half22float2(vh[e]);
        int j = part*8 + e*2;
        qs[row][j] = fq.x; qs[row][j+1] = fq.y;
        ks[row][j] = fk.x; ks[row][j+1] = fk.y;
        vs[row][j] = fv.x; vs[row][j+1] = fv.y;
    }
    __syncthreads();

    const float inv_log16_x8 = 8.f / logf(16.f);
    for (int e = tid; e < 256; e += 128) {
        int i = e >> 4, j = e & 15;
        float d = 0.f;
        #pragma unroll
        for (int c = 0; c < 64; c++) d += qs[i][c]*ks[j][c];
        int rp = j - i;
        int ret = (rp > 0) ? 16 : 0;
        int n = rp < 0 ? -rp : rp;
        int bkt;
        if (n < 8) bkt = ret + n;
        else {
            int vl = 8 + (int)(logf((float)n * 0.125f) * inv_log16_x8);
            bkt = ret + (vl < 15 ? vl : 15);
        }
        P[i][j] = d * 0.125f + tab[bkt*NH + h];
    }
    __syncthreads();
    if (tid < 16) {
        float m = -1e30f;
        #pragma unroll
        for (int j = 0; j < 16; j++) m = fmaxf(m, P[tid][j]);
        float sum = 0.f;
        #pragma unroll
        for (int j = 0; j < 16; j++) { float e = expf(P[tid][j]-m); P[tid][j] = e; sum += e; }
        float inv = 1.f / sum;
        #pragma unroll
        for (int j = 0; j < 16; j++) P[tid][j] *= inv;
    }
    __syncthreads();

    float o[8] = {0,0,0,0,0,0,0,0};
    #pragma unroll
    for (int t2 = 0; t2 < 16; t2++) {
        float p = P[row][t2];
        #pragma unroll
        for (int e = 0; e < 8; e++) o[e] += p * vs[t2][part*8+e];
    }
    unsigned H[4];
    #pragma unroll
    for (int e = 0; e < 4; e++) {
        __half2 hh = __floats2half2_rn(o[2*e], o[2*e+1]);
        H[e] = *(unsigned*)&hh;
    }
    size_t off = ((size_t)row*SPA + s)*C_ + h*HD + part*8;
    *(uint4*)(g_oh + off) = make_uint4(H[0], H[1], H[2], H[3]);
}

// ---------------------------------------------------------------------------
// Kernel 6: output GEMM + bias + residual
// ---------------------------------------------------------------------------
__global__ void __launch_bounds__(256, 2) out_gemm_tc(const float* __restrict__ x,
                                                      const float* __restrict__ bias,
                                                      float* __restrict__ y) {
    extern __shared__ char smem[];
    uint32_t sb = smem_u32(smem);
    int tid = threadIdx.x;
    int bn = blockIdx.x * 128, bm = blockIdx.y * 128;
    int r = tid >> 1, part = tid & 1;
    const char* aSrc = (const char*)(g_oh  + (size_t)(bm + r)*C_) + part*64;
    const char* bSrc = (const char*)(g_woh + (size_t)(bn + r)*C_) + part*64;

    float acc[2][8][4] = {};
    mma_mainloop(acc, aSrc, bSrc, sb);
    __syncthreads();
    float* st = (float*)smem;
    stage_acc(acc, st);
    __syncthreads();

    int n = bn + (tid >> 1);
    int sh_ = tid & 1;
    int t = bm >> 11, s0 = bm & (SPA-1);
    size_t off = (size_t)t*C_*SPA + (size_t)n*SPA + s0 + sh_*64;
    float bb = bias[n];
    const float* src = st + sh_*64*132 + (n - bn);
    #pragma unroll
    for (int i = 0; i < 64; i += 4) {
        float4 rx = *(const float4*)(x + off + i);
        float4 v = make_float4(src[(i+0)*132], src[(i+1)*132],
                               src[(i+2)*132], src[(i+3)*132]);
        v.x += bb + rx.x; v.y += bb + rx.y; v.z += bb + rx.z; v.w += bb + rx.w;
        *(float4*)(y + off + i) = v;
    }
}

// ---------------------------------------------------------------------------
extern "C" void kernel_launch(void* const* d_in, const int* in_sizes, int n_in,
                              void* d_out, int out_size) {
    const float* x     = (const float*)d_in[0];
    const float* nw    = (const float*)d_in[1];
    const float* w_in  = (const float*)d_in[2];
    const float* b_in  = (const float*)d_in[3];
    const float* qsc   = (const float*)d_in[4];
    const float* qbi   = (const float*)d_in[5];
    const float* ksc   = (const float*)d_in[6];
    const float* kbi   = (const float*)d_in[7];
    const float* tab   = (const float*)d_in[8];
    const float* w_out = (const float*)d_in[9];
    const float* b_out = (const float*)d_in[10];
    float* y = (float*)d_out;

    cudaFuncSetAttribute(qkv_gemm_tc, cudaFuncAttributeMaxDynamicSharedMemorySize, SMEM_GEMM);
    cudaFuncSetAttribute(out_gemm_tc, cudaFuncAttributeMaxDynamicSharedMemorySize, SMEM_GEMM);

    gn_stats_kernel<<<T_*NH, 256>>>(x);
    prep_w_kernel<<<(N1*C_/4 + C_*C_/4)/256, 256>>>(w_in, w_out);
    prep_x_kernel<<<dim3(M_/64, C_/64), 256>>>(x, nw);
    qkv_gemm_tc<<<dim3(N1/128, M_/128), 256, SMEM_GEMM>>>(b_in, qsc, qbi, ksc, kbi);
    attn_kernel<<<SPA*NH, 128>>>(tab);
    out_gemm_tc<<<dim3(C_/128, M_/128), 256, SMEM_GEMM>>>(x, b_out, y);
}